// round 5
// baseline (speedup 1.0000x reference)
#include <cuda_runtime.h>
#include <cstdint>
#include <cstddef>

#define DEV_INLINE __device__ __forceinline__

// ---------------- problem constants ----------------
constexpr int B_ = 8, C_ = 3, H_ = 128;
constexpr int D_ = 2048, F_ = 8192, NC_ = 1000;
constexpr int TOK = B_ * C_ * H_;          // 3072
constexpr size_t WELEM = (size_t)F_ * D_;  // 16777216

// ---------------- GEMM tiling ----------------
constexpr int TILE_M = 128, TILE_N = 64, KC = 64;   // KC bytes of K per chunk
constexpr int NCHUNK = D_ / KC;                     // 32
constexpr int ROWB = 80;                            // padded SMEM row stride (bytes)
constexpr int OFF_A  = 0;                           // 128 rows x 80B = 10240
constexpr int OFF_BG = 10240;                       // 64 x 80 = 5120
constexpr int OFF_BU = 15360;                       // 64 x 80 = 5120
constexpr int STAGE_B = 20480;
constexpr int SMEM_BYTES = 2 * STAGE_B;             // 40960 (also reused by epilogue)
constexpr int EPI_STRIDE = 66;                      // floats per row in epilogue tile

// ---------------- scratch globals (no cudaMalloc allowed) ----------------
__device__ __align__(128) float  g_hbuf[(size_t)TOK * F_];   // ~100 MB
__device__ __align__(128) int8_t g_wgq8[WELEM];
__device__ __align__(128) int8_t g_wuq8[WELEM];
__device__ __align__(128) int8_t g_xq8[(size_t)TOK * D_];
__device__ float g_sa[TOK];          // per-token act scale s = 127/absmax
__device__ float g_wdsum[F_];        // integer column sums of ternary Wd
__device__ float g_tokval[TOK];
__device__ float g_pooled[B_ * C_];
__device__ float g_part[3 * 2048];   // per-block |W| partial sums
__device__ float g_scales[3];        // 1/clip(mean|W|,1e-5) for g,u,d

// ---------------- PTX helpers (all plain-sm_103-safe: cp.async + mma.sync) ---
DEV_INLINE uint32_t smem_u32(const void* p) {
    uint32_t a;
    asm("{ .reg .u64 t; cvta.to.shared.u64 t, %1; cvt.u32.u64 %0, t; }"
        : "=r"(a) : "l"(p));
    return a;
}
#define CP_ASYNC16(saddr, gptr) \
    asm volatile("cp.async.cg.shared.global [%0], [%1], 16;" \
                 :: "r"(saddr), "l"(gptr) : "memory")
#define CP_COMMIT() asm volatile("cp.async.commit_group;" ::: "memory")
#define CP_WAIT1()  asm volatile("cp.async.wait_group 1;" ::: "memory")
#define CP_WAIT0()  asm volatile("cp.async.wait_group 0;" ::: "memory")

#define MMA_S8(c, a, b) \
    asm volatile("mma.sync.aligned.m16n8k32.row.col.s32.s8.s8.s32 " \
                 "{%0,%1,%2,%3}, {%4,%5,%6,%7}, {%8,%9}, {%0,%1,%2,%3};" \
                 : "+r"((c)[0]), "+r"((c)[1]), "+r"((c)[2]), "+r"((c)[3]) \
                 : "r"((a)[0]), "r"((a)[1]), "r"((a)[2]), "r"((a)[3]), \
                   "r"((b)[0]), "r"((b)[1]))

DEV_INLINE float warp_sum(float v) {
    #pragma unroll
    for (int o = 16; o; o >>= 1) v += __shfl_xor_sync(0xFFFFFFFFu, v, o);
    return v;
}
DEV_INLINE float warp_max(float v) {
    #pragma unroll
    for (int o = 16; o; o >>= 1) v = fmaxf(v, __shfl_xor_sync(0xFFFFFFFFu, v, o));
    return v;
}
DEV_INLINE int8_t q8(float v, float s, float lo, float hi) {
    return (int8_t)(int)fminf(fmaxf(rintf(v * s), lo), hi);
}

// ============ K0: zero accumulators (graph replays reuse globals) ============
__global__ void k_zero() {
    int i = blockIdx.x * 256 + threadIdx.x;
    if (i < F_) g_wdsum[i] = 0.f;
}

// ============ K1: per-block partial sums of |W|   grid (2048,3) x 256 ========
__global__ void __launch_bounds__(256) k_absmean(const float* __restrict__ A,
                                                 const float* __restrict__ Bm,
                                                 const float* __restrict__ Cm) {
    const float* p = (blockIdx.y == 0) ? A : (blockIdx.y == 1) ? Bm : Cm;
    const float4* p4 = (const float4*)p;
    size_t base = (size_t)blockIdx.x * 2048;
    float s = 0.f;
    #pragma unroll
    for (int i = 0; i < 8; i++) {
        float4 v = p4[base + i * 256 + threadIdx.x];
        s += fabsf(v.x) + fabsf(v.y) + fabsf(v.z) + fabsf(v.w);
    }
    s = warp_sum(s);
    __shared__ float red[8];
    if ((threadIdx.x & 31) == 0) red[threadIdx.x >> 5] = s;
    __syncthreads();
    if (threadIdx.x == 0) {
        float t = 0.f;
        #pragma unroll
        for (int i = 0; i < 8; i++) t += red[i];
        g_part[blockIdx.y * 2048 + blockIdx.x] = t;
    }
}

// ============ K2: deterministic scale finalize (1 block) =====================
__global__ void __launch_bounds__(256) k_scales() {
    __shared__ double sr[256];
    int tid = threadIdx.x;
    for (int m = 0; m < 3; m++) {
        double a = 0.0;
        for (int j = tid; j < 2048; j += 256) a += (double)g_part[m * 2048 + j];
        sr[tid] = a;
        __syncthreads();
        for (int s = 128; s; s >>= 1) {
            if (tid < s) sr[tid] += sr[tid + s];
            __syncthreads();
        }
        if (tid == 0) {
            float mean = (float)(sr[0] / (double)WELEM);
            g_scales[m] = 1.f / fmaxf(mean, 1e-5f);
        }
        __syncthreads();
    }
}

// ============ K3: ternary-quantize Wg/Wu -> int8   grid (2048,2) x 256 =======
__global__ void __launch_bounds__(256) k_quantw(const float* __restrict__ Wg,
                                                const float* __restrict__ Wu) {
    const float* src = blockIdx.y ? Wu : Wg;
    int8_t* dst = blockIdx.y ? g_wuq8 : g_wgq8;
    float s = g_scales[blockIdx.y];
    const float4* s4 = (const float4*)src;
    char4* d4 = (char4*)dst;
    size_t base = (size_t)blockIdx.x * 2048;
    #pragma unroll
    for (int i = 0; i < 8; i++) {
        size_t idx = base + i * 256 + threadIdx.x;
        float4 v = s4[idx];
        char4 o;
        o.x = q8(v.x, s, -1.f, 1.f);
        o.y = q8(v.y, s, -1.f, 1.f);
        o.z = q8(v.z, s, -1.f, 1.f);
        o.w = q8(v.w, s, -1.f, 1.f);
        d4[idx] = o;
    }
}

// ============ K4: wd_sum[f] += sum over 128 rows (exact int atomics) =========
__global__ void __launch_bounds__(256) k_wdsum(const float* __restrict__ Wd) {
    int t = blockIdx.x * 256 + threadIdx.x;   // 0..131071
    int f = t & (F_ - 1);
    int seg = t >> 13;                        // 16 segments x 128 rows
    float s = g_scales[2];
    const float* p = Wd + (size_t)seg * 128 * F_ + f;
    float acc = 0.f;
    #pragma unroll 8
    for (int d = 0; d < 128; d++)
        acc += fminf(fmaxf(rintf(p[(size_t)d * F_] * s), -1.f), 1.f);
    atomicAdd(&g_wdsum[f], acc);
}

// ============ K5: per-token int8 activation quant   grid 3072 x 256 ==========
__global__ void __launch_bounds__(256) k_xquant(const float* __restrict__ x) {
    __shared__ float red[8];
    __shared__ float sc;
    int t = blockIdx.x, tid = threadIdx.x;
    const float4* xr = (const float4*)(x + (size_t)t * D_);
    float4 a = xr[tid], b = xr[256 + tid];
    float am = fmaxf(fmaxf(fabsf(a.x), fabsf(a.y)), fmaxf(fabsf(a.z), fabsf(a.w)));
    am = fmaxf(am, fmaxf(fmaxf(fabsf(b.x), fabsf(b.y)), fmaxf(fabsf(b.z), fabsf(b.w))));
    am = warp_max(am);
    if ((tid & 31) == 0) red[tid >> 5] = am;
    __syncthreads();
    if (tid == 0) {
        float m = red[0];
        #pragma unroll
        for (int i = 1; i < 8; i++) m = fmaxf(m, red[i]);
        float s = 127.f / fmaxf(m, 1e-5f);
        sc = s;
        g_sa[t] = s;
    }
    __syncthreads();
    float s = sc;
    char4* d4 = (char4*)(g_xq8 + (size_t)t * D_);
    char4 o;
    o.x = q8(a.x, s, -128.f, 127.f);
    o.y = q8(a.y, s, -128.f, 127.f);
    o.z = q8(a.z, s, -128.f, 127.f);
    o.w = q8(a.w, s, -128.f, 127.f);
    d4[tid] = o;
    o.x = q8(b.x, s, -128.f, 127.f);
    o.y = q8(b.y, s, -128.f, 127.f);
    o.z = q8(b.z, s, -128.f, 127.f);
    o.w = q8(b.w, s, -128.f, 127.f);
    d4[256 + tid] = o;
}

// ============ K6: int8 mma.sync GEMM (g & u) + fused SiLU epilogue ===========
__global__ void __launch_bounds__(256, 2) k_gemm() {
    __shared__ __align__(16) char smem[SMEM_BYTES];
    int tid = threadIdx.x;
    int wid = tid >> 5, l = tid & 31;
    int f0 = blockIdx.x * TILE_N;
    int tok0 = blockIdx.y * TILE_M;
    uint32_t sb = smem_u32(smem);

    int c[2][8][4];
    #pragma unroll
    for (int mi = 0; mi < 2; mi++)
        #pragma unroll
        for (int ni = 0; ni < 8; ni++)
            #pragma unroll
            for (int j = 0; j < 4; j++) c[mi][ni][j] = 0;

    // ---- stage loader: 4 x 16B cp.async per thread ----
    auto load_stage = [&](int ch, int st) {
        uint32_t base = sb + st * STAGE_B;
        #pragma unroll
        for (int h = 0; h < 2; h++) {
            int idx = tid + h * 256;           // 0..511 -> A rows
            int r = idx >> 2, sg = idx & 3;
            const int8_t* gp = g_xq8 + (size_t)(tok0 + r) * D_ + ch * KC + sg * 16;
            CP_ASYNC16(base + OFF_A + r * ROWB + sg * 16, gp);
        }
        {
            int r = tid >> 2, sg = tid & 3;    // 64 B rows x 4 segs
            const int8_t* gg = g_wgq8 + (size_t)(f0 + r) * D_ + ch * KC + sg * 16;
            CP_ASYNC16(base + OFF_BG + r * ROWB + sg * 16, gg);
            const int8_t* gu = g_wuq8 + (size_t)(f0 + r) * D_ + ch * KC + sg * 16;
            CP_ASYNC16(base + OFF_BU + r * ROWB + sg * 16, gu);
        }
        CP_COMMIT();
    };

    load_stage(0, 0);

    int m0 = (wid & 3) * 32;
    const char* bsel_off0 = smem + ((wid < 4) ? OFF_BG : OFF_BU);

    #pragma unroll 1
    for (int i = 0; i < NCHUNK; i++) {
        if (i + 1 < NCHUNK) load_stage(i + 1, (i + 1) & 1);
        if (i + 1 < NCHUNK) { CP_WAIT1(); } else { CP_WAIT0(); }
        __syncthreads();

        const char* stA = smem + (i & 1) * STAGE_B + OFF_A;
        const char* stB = bsel_off0 + (i & 1) * STAGE_B;

        #pragma unroll
        for (int ks = 0; ks < 2; ks++) {
            int kb = ks * 32 + (l & 3) * 4;
            uint32_t a[2][4];
            #pragma unroll
            for (int mi = 0; mi < 2; mi++) {
                int r = m0 + mi * 16 + (l >> 2);
                a[mi][0] = *(const uint32_t*)(stA + r * ROWB + kb);
                a[mi][1] = *(const uint32_t*)(stA + (r + 8) * ROWB + kb);
                a[mi][2] = *(const uint32_t*)(stA + r * ROWB + kb + 16);
                a[mi][3] = *(const uint32_t*)(stA + (r + 8) * ROWB + kb + 16);
            }
            uint32_t b[8][2];
            #pragma unroll
            for (int ni = 0; ni < 8; ni++) {
                int rn = ni * 8 + (l >> 2);
                b[ni][0] = *(const uint32_t*)(stB + rn * ROWB + kb);
                b[ni][1] = *(const uint32_t*)(stB + rn * ROWB + kb + 16);
            }
            #pragma unroll
            for (int mi = 0; mi < 2; mi++)
                #pragma unroll
                for (int ni = 0; ni < 8; ni++)
                    MMA_S8(c[mi][ni], a[mi], b[ni]);
        }
        __syncthreads();
    }

    // ---- fused epilogue: g warps -> silu to smem; u warps -> multiply+store --
    float* hf = (float*)smem;   // [128][EPI_STRIDE]
    if (wid < 4) {
        float sg = g_scales[0];
        #pragma unroll
        for (int mi = 0; mi < 2; mi++) {
            int r0 = m0 + mi * 16 + (l >> 2);
            int r1 = r0 + 8;
            float i0 = 1.f / (g_sa[tok0 + r0] * sg);
            float i1 = 1.f / (g_sa[tok0 + r1] * sg);
            #pragma unroll
            for (int ni = 0; ni < 8; ni++) {
                int col = ni * 8 + (l & 3) * 2;
                float g0 = (float)c[mi][ni][0] * i0;
                float g1 = (float)c[mi][ni][1] * i0;
                float g2 = (float)c[mi][ni][2] * i1;
                float g3 = (float)c[mi][ni][3] * i1;
                hf[r0 * EPI_STRIDE + col]     = g0 / (1.f + __expf(-g0));
                hf[r0 * EPI_STRIDE + col + 1] = g1 / (1.f + __expf(-g1));
                hf[r1 * EPI_STRIDE + col]     = g2 / (1.f + __expf(-g2));
                hf[r1 * EPI_STRIDE + col + 1] = g3 / (1.f + __expf(-g3));
            }
        }
    }
    __syncthreads();
    if (wid >= 4) {
        float su = g_scales[1];
        #pragma unroll
        for (int mi = 0; mi < 2; mi++) {
            int r0 = m0 + mi * 16 + (l >> 2);
            int r1 = r0 + 8;
            float i0 = 1.f / (g_sa[tok0 + r0] * su);
            float i1 = 1.f / (g_sa[tok0 + r1] * su);
            float* o0 = g_hbuf + (size_t)(tok0 + r0) * F_ + f0;
            float* o1 = g_hbuf + (size_t)(tok0 + r1) * F_ + f0;
            #pragma unroll
            for (int ni = 0; ni < 8; ni++) {
                int col = ni * 8 + (l & 3) * 2;
                float2 v0, v1;
                v0.x = hf[r0 * EPI_STRIDE + col]     * ((float)c[mi][ni][0] * i0);
                v0.y = hf[r0 * EPI_STRIDE + col + 1] * ((float)c[mi][ni][1] * i0);
                v1.x = hf[r1 * EPI_STRIDE + col]     * ((float)c[mi][ni][2] * i1);
                v1.y = hf[r1 * EPI_STRIDE + col + 1] * ((float)c[mi][ni][3] * i1);
                *(float2*)(o0 + col) = v0;
                *(float2*)(o1 + col) = v1;
            }
        }
    }
}

// ============ K7: rmsnorm + act-quant + dot(wd_sum)   grid 3072 x 256 ========
__global__ void __launch_bounds__(256) k_token(const float* __restrict__ lnw) {
    __shared__ float sh[F_];
    __shared__ float red[8];
    __shared__ float bc;
    int t = blockIdx.x, tid = threadIdx.x;
    int w = tid >> 5, l = tid & 31;
    const float4* src = (const float4*)(g_hbuf + (size_t)t * F_);
    float ss = 0.f;
    #pragma unroll
    for (int i = 0; i < 8; i++) {
        float4 v = src[i * 256 + tid];
        ((float4*)sh)[i * 256 + tid] = v;
        ss += v.x * v.x + v.y * v.y + v.z * v.z + v.w * v.w;
    }
    ss = warp_sum(ss);
    if (l == 0) red[w] = ss;
    __syncthreads();
    if (tid == 0) {
        float tot = 0.f;
        #pragma unroll
        for (int i = 0; i < 8; i++) tot += red[i];
        bc = rsqrtf(tot / (float)F_ + 1e-6f);
    }
    __syncthreads();
    float rs = bc;
    float am = 0.f;
    const float4* w4 = (const float4*)lnw;
    #pragma unroll
    for (int i = 0; i < 8; i++) {
        int idx = i * 256 + tid;
        float4 h = ((float4*)sh)[idx];
        float4 g = w4[idx];
        am = fmaxf(am, fabsf(h.x * rs * g.x));
        am = fmaxf(am, fabsf(h.y * rs * g.y));
        am = fmaxf(am, fabsf(h.z * rs * g.z));
        am = fmaxf(am, fabsf(h.w * rs * g.w));
    }
    am = warp_max(am);
    if (l == 0) red[w] = am;
    __syncthreads();
    if (tid == 0) {
        float m = red[0];
        #pragma unroll
        for (int i = 1; i < 8; i++) m = fmaxf(m, red[i]);
        bc = 127.f / fmaxf(m, 1e-5f);
    }
    __syncthreads();
    float s2 = bc;
    const float4* ws = (const float4*)g_wdsum;
    float acc = 0.f;
    #pragma unroll
    for (int i = 0; i < 8; i++) {
        int idx = i * 256 + tid;
        float4 h = ((float4*)sh)[idx];
        float4 g = w4[idx];
        float4 d = ws[idx];
        acc += fminf(fmaxf(rintf(h.x * rs * g.x * s2), -128.f), 127.f) * d.x;
        acc += fminf(fmaxf(rintf(h.y * rs * g.y * s2), -128.f), 127.f) * d.y;
        acc += fminf(fmaxf(rintf(h.z * rs * g.z * s2), -128.f), 127.f) * d.z;
        acc += fminf(fmaxf(rintf(h.w * rs * g.w * s2), -128.f), 127.f) * d.w;
    }
    acc = warp_sum(acc);
    if (l == 0) red[w] = acc;
    __syncthreads();
    if (tid == 0) {
        float tot = 0.f;
        #pragma unroll
        for (int i = 0; i < 8; i++) tot += red[i];
        g_tokval[t] = tot / s2;
    }
}

// ============ K8: pooled[b,c] ================================================
__global__ void k_pool() {
    int tid = threadIdx.x, w = tid >> 5, l = tid & 31;
    float inv = 1.f / (g_scales[2] * (float)H_ * (float)D_);
    for (int combo = w; combo < B_ * C_; combo += 8) {
        float s = 0.f;
        #pragma unroll
        for (int j = l; j < H_; j += 32) s += g_tokval[combo * H_ + j];
        s = warp_sum(s);
        if (l == 0) g_pooled[combo] = s * inv;
    }
}

// ============ K9: classifier =================================================
__global__ void k_cls(const float* __restrict__ cW, const float* __restrict__ cb,
                      float* __restrict__ out) {
    int i = blockIdx.x * 256 + threadIdx.x;
    if (i < B_ * NC_) {
        int b = i / NC_, n = i - b * NC_;
        float v = cb[n];
        v += g_pooled[b * 3 + 0] * cW[n * 3 + 0];
        v += g_pooled[b * 3 + 1] * cW[n * 3 + 1];
        v += g_pooled[b * 3 + 2] * cW[n * 3 + 2];
        out[i] = v;
    }
}

// ============ host ==========================================================
extern "C" void kernel_launch(void* const* d_in, const int* in_sizes, int n_in,
                              void* d_out, int out_size) {
    const float* x    = (const float*)d_in[0];
    const float* Wg   = (const float*)d_in[1];
    const float* Wu   = (const float*)d_in[2];
    const float* Wd   = (const float*)d_in[3];
    const float* lnw  = (const float*)d_in[4];
    const float* clsW = (const float*)d_in[5];
    const float* clsb = (const float*)d_in[6];
    float* out = (float*)d_out;

    k_zero<<<32, 256>>>();
    k_absmean<<<dim3(2048, 3), 256>>>(Wg, Wu, Wd);
    k_scales<<<1, 256>>>();
    k_quantw<<<dim3(2048, 2), 256>>>(Wg, Wu);
    k_wdsum<<<512, 256>>>(Wd);
    k_xquant<<<TOK, 256>>>(x);
    k_gemm<<<dim3(F_ / TILE_N, TOK / TILE_M), 256>>>();
    k_token<<<TOK, 256>>>(lnw);
    k_pool<<<1, 256>>>();
    k_cls<<<32, 256>>>(clsW, clsb, out);
}

// round 6
// speedup vs baseline: 1.0270x; 1.0270x over previous
#include <cuda_runtime.h>
#include <cstdint>
#include <cstddef>

#define DEV_INLINE __device__ __forceinline__

// ---------------- problem constants ----------------
constexpr int B_ = 8, C_ = 3, H_ = 128;
constexpr int D_ = 2048, F_ = 8192, NC_ = 1000;
constexpr int TOK = B_ * C_ * H_;          // 3072
constexpr size_t WELEM = (size_t)F_ * D_;  // 16777216

// ---------------- GEMM tiling ----------------
constexpr int TILE_M = 128, TILE_N = 64, KC = 64;   // KC bytes of K per chunk
constexpr int NCHUNK = D_ / KC;                     // 32
constexpr int ROWB = 80;                            // padded SMEM row stride (bytes)
constexpr int OFF_A  = 0;                           // 128 rows x 80B = 10240
constexpr int OFF_BG = 10240;                       // 64 x 80 = 5120
constexpr int OFF_BU = 15360;                       // 64 x 80 = 5120
constexpr int STAGE_B = 20480;
constexpr int NSTAGE = 4;
constexpr int SMEM_DYN = NSTAGE * STAGE_B;          // 81920 (epilogue reuses it)
constexpr int EPI_STRIDE = 66;                      // floats per row in epilogue tile

// ---------------- scratch globals (no cudaMalloc allowed) ----------------
__device__ __align__(128) float  g_hbuf[(size_t)TOK * F_];   // ~100 MB
__device__ __align__(128) int8_t g_wgq8[WELEM];
__device__ __align__(128) int8_t g_wuq8[WELEM];
__device__ __align__(128) int8_t g_xq8[(size_t)TOK * D_];
__device__ float g_sa[TOK];          // per-token act scale s = 127/absmax
__device__ float g_wdsum[F_];        // integer column sums of ternary Wd
__device__ float g_tokval[TOK];
__device__ float g_pooled[B_ * C_];
__device__ float g_part[3 * 2048];   // per-block |W| partial sums
__device__ float g_scales[3];        // 1/clip(mean|W|,1e-5) for g,u,d

// ---------------- PTX helpers (plain-sm_103-safe: cp.async + mma.sync) -------
DEV_INLINE uint32_t smem_u32(const void* p) {
    uint32_t a;
    asm("{ .reg .u64 t; cvta.to.shared.u64 t, %1; cvt.u32.u64 %0, t; }"
        : "=r"(a) : "l"(p));
    return a;
}
#define CP_ASYNC16(saddr, gptr) \
    asm volatile("cp.async.cg.shared.global [%0], [%1], 16;" \
                 :: "r"(saddr), "l"(gptr) : "memory")
#define CP_COMMIT() asm volatile("cp.async.commit_group;" ::: "memory")
#define CP_WAIT2()  asm volatile("cp.async.wait_group 2;" ::: "memory")
#define CP_WAIT0()  asm volatile("cp.async.wait_group 0;" ::: "memory")

#define MMA_S8(c, a, b) \
    asm volatile("mma.sync.aligned.m16n8k32.row.col.s32.s8.s8.s32 " \
                 "{%0,%1,%2,%3}, {%4,%5,%6,%7}, {%8,%9}, {%0,%1,%2,%3};" \
                 : "+r"((c)[0]), "+r"((c)[1]), "+r"((c)[2]), "+r"((c)[3]) \
                 : "r"((a)[0]), "r"((a)[1]), "r"((a)[2]), "r"((a)[3]), \
                   "r"((b)[0]), "r"((b)[1]))

DEV_INLINE float warp_sum(float v) {
    #pragma unroll
    for (int o = 16; o; o >>= 1) v += __shfl_xor_sync(0xFFFFFFFFu, v, o);
    return v;
}
DEV_INLINE float warp_max(float v) {
    #pragma unroll
    for (int o = 16; o; o >>= 1) v = fmaxf(v, __shfl_xor_sync(0xFFFFFFFFu, v, o));
    return v;
}
DEV_INLINE int8_t q8(float v, float s, float lo, float hi) {
    return (int8_t)(int)fminf(fmaxf(rintf(v * s), lo), hi);
}

// ============ K0: zero accumulators ==========================================
__global__ void k_zero() {
    int i = blockIdx.x * 256 + threadIdx.x;
    if (i < F_) g_wdsum[i] = 0.f;
}

// ============ K1: per-block partial sums of |W|   grid (2048,3) x 256 ========
__global__ void __launch_bounds__(256) k_absmean(const float* __restrict__ A,
                                                 const float* __restrict__ Bm,
                                                 const float* __restrict__ Cm) {
    const float* p = (blockIdx.y == 0) ? A : (blockIdx.y == 1) ? Bm : Cm;
    const float4* p4 = (const float4*)p;
    size_t base = (size_t)blockIdx.x * 2048;
    float s = 0.f;
    #pragma unroll
    for (int i = 0; i < 8; i++) {
        float4 v = p4[base + i * 256 + threadIdx.x];
        s += fabsf(v.x) + fabsf(v.y) + fabsf(v.z) + fabsf(v.w);
    }
    s = warp_sum(s);
    __shared__ float red[8];
    if ((threadIdx.x & 31) == 0) red[threadIdx.x >> 5] = s;
    __syncthreads();
    if (threadIdx.x == 0) {
        float t = 0.f;
        #pragma unroll
        for (int i = 0; i < 8; i++) t += red[i];
        g_part[blockIdx.y * 2048 + blockIdx.x] = t;
    }
}

// ============ K2: deterministic scale finalize (1 block) =====================
__global__ void __launch_bounds__(256) k_scales() {
    __shared__ double sr[256];
    int tid = threadIdx.x;
    for (int m = 0; m < 3; m++) {
        double a = 0.0;
        for (int j = tid; j < 2048; j += 256) a += (double)g_part[m * 2048 + j];
        sr[tid] = a;
        __syncthreads();
        for (int s = 128; s; s >>= 1) {
            if (tid < s) sr[tid] += sr[tid + s];
            __syncthreads();
        }
        if (tid == 0) {
            float mean = (float)(sr[0] / (double)WELEM);
            g_scales[m] = 1.f / fmaxf(mean, 1e-5f);
        }
        __syncthreads();
    }
}

// ============ K3: ternary-quantize Wg/Wu -> int8   grid (2048,2) x 256 =======
__global__ void __launch_bounds__(256) k_quantw(const float* __restrict__ Wg,
                                                const float* __restrict__ Wu) {
    const float* src = blockIdx.y ? Wu : Wg;
    int8_t* dst = blockIdx.y ? g_wuq8 : g_wgq8;
    float s = g_scales[blockIdx.y];
    const float4* s4 = (const float4*)src;
    char4* d4 = (char4*)dst;
    size_t base = (size_t)blockIdx.x * 2048;
    #pragma unroll
    for (int i = 0; i < 8; i++) {
        size_t idx = base + i * 256 + threadIdx.x;
        float4 v = s4[idx];
        char4 o;
        o.x = q8(v.x, s, -1.f, 1.f);
        o.y = q8(v.y, s, -1.f, 1.f);
        o.z = q8(v.z, s, -1.f, 1.f);
        o.w = q8(v.w, s, -1.f, 1.f);
        d4[idx] = o;
    }
}

// ============ K4: wd_sum[f] += sum over 128 rows (exact int atomics) =========
__global__ void __launch_bounds__(256) k_wdsum(const float* __restrict__ Wd) {
    int t = blockIdx.x * 256 + threadIdx.x;   // 0..131071
    int f = t & (F_ - 1);
    int seg = t >> 13;                        // 16 segments x 128 rows
    float s = g_scales[2];
    const float* p = Wd + (size_t)seg * 128 * F_ + f;
    float acc = 0.f;
    #pragma unroll 8
    for (int d = 0; d < 128; d++)
        acc += fminf(fmaxf(rintf(p[(size_t)d * F_] * s), -1.f), 1.f);
    atomicAdd(&g_wdsum[f], acc);
}

// ============ K5: per-token int8 activation quant   grid 3072 x 256 ==========
__global__ void __launch_bounds__(256) k_xquant(const float* __restrict__ x) {
    __shared__ float red[8];
    __shared__ float sc;
    int t = blockIdx.x, tid = threadIdx.x;
    const float4* xr = (const float4*)(x + (size_t)t * D_);
    float4 a = xr[tid], b = xr[256 + tid];
    float am = fmaxf(fmaxf(fabsf(a.x), fabsf(a.y)), fmaxf(fabsf(a.z), fabsf(a.w)));
    am = fmaxf(am, fmaxf(fmaxf(fabsf(b.x), fabsf(b.y)), fmaxf(fabsf(b.z), fabsf(b.w))));
    am = warp_max(am);
    if ((tid & 31) == 0) red[tid >> 5] = am;
    __syncthreads();
    if (tid == 0) {
        float m = red[0];
        #pragma unroll
        for (int i = 1; i < 8; i++) m = fmaxf(m, red[i]);
        float s = 127.f / fmaxf(m, 1e-5f);
        sc = s;
        g_sa[t] = s;
    }
    __syncthreads();
    float s = sc;
    char4* d4 = (char4*)(g_xq8 + (size_t)t * D_);
    char4 o;
    o.x = q8(a.x, s, -128.f, 127.f);
    o.y = q8(a.y, s, -128.f, 127.f);
    o.z = q8(a.z, s, -128.f, 127.f);
    o.w = q8(a.w, s, -128.f, 127.f);
    d4[tid] = o;
    o.x = q8(b.x, s, -128.f, 127.f);
    o.y = q8(b.y, s, -128.f, 127.f);
    o.z = q8(b.z, s, -128.f, 127.f);
    o.w = q8(b.w, s, -128.f, 127.f);
    d4[256 + tid] = o;
}

// ============ K6: int8 mma.sync GEMM (g & u) + fused SiLU epilogue ===========
// 512 threads. Warps 0-7 -> g, 8-15 -> u. Warp tile 32x32 (c = 32 regs, no
// spills). 4-stage cp.async ring, ONE barrier per chunk.
__global__ void __launch_bounds__(512, 1) k_gemm() {
    extern __shared__ __align__(16) char smem[];
    int tid = threadIdx.x;
    int wid = tid >> 5, l = tid & 31;
    int f0 = blockIdx.x * TILE_N;
    int tok0 = blockIdx.y * TILE_M;
    uint32_t sb = smem_u32(smem);

    int gsel = wid >> 3;          // 0 = g, 1 = u
    int wq = wid & 7;
    int m0 = (wq & 3) * 32;
    int n0 = (wq >> 2) * 32;

    int c[2][4][4];
    #pragma unroll
    for (int mi = 0; mi < 2; mi++)
        #pragma unroll
        for (int ni = 0; ni < 4; ni++)
            #pragma unroll
            for (int j = 0; j < 4; j++) c[mi][ni][j] = 0;

    // ---- stage loader: 2 x 16B cp.async per thread ----
    auto load_stage = [&](int ch, int st) {
        uint32_t base = sb + st * STAGE_B;
        {   // A: 128 rows x 64B = 512 x 16B
            int r = tid >> 2, sg = tid & 3;
            const int8_t* gp = g_xq8 + (size_t)(tok0 + r) * D_ + ch * KC + sg * 16;
            CP_ASYNC16(base + OFF_A + r * ROWB + sg * 16, gp);
        }
        {   // B: threads 0-255 -> g rows, 256-511 -> u rows
            int r = (tid & 255) >> 2, sg = tid & 3;
            const int8_t* w = (tid < 256 ? g_wgq8 : g_wuq8)
                              + (size_t)(f0 + r) * D_ + ch * KC + sg * 16;
            uint32_t off = (tid < 256) ? (uint32_t)OFF_BG : (uint32_t)OFF_BU;
            CP_ASYNC16(base + off + r * ROWB + sg * 16, w);
        }
        CP_COMMIT();
    };

    load_stage(0, 0);
    load_stage(1, 1);

    const char* bbase0 = smem + (gsel ? OFF_BU : OFF_BG);

    #pragma unroll 1
    for (int i = 0; i < NCHUNK; i++) {
        if (i + 2 < NCHUNK) {
            load_stage(i + 2, (i + 2) & 3);
            CP_WAIT2();
        } else {
            CP_WAIT0();
        }
        __syncthreads();

        const char* stA = smem + (i & 3) * STAGE_B + OFF_A;
        const char* stB = bbase0 + (i & 3) * STAGE_B;

        #pragma unroll
        for (int ks = 0; ks < 2; ks++) {
            int kb = ks * 32 + (l & 3) * 4;
            uint32_t a[2][4];
            #pragma unroll
            for (int mi = 0; mi < 2; mi++) {
                int r = m0 + mi * 16 + (l >> 2);
                a[mi][0] = *(const uint32_t*)(stA + r * ROWB + kb);
                a[mi][1] = *(const uint32_t*)(stA + (r + 8) * ROWB + kb);
                a[mi][2] = *(const uint32_t*)(stA + r * ROWB + kb + 16);
                a[mi][3] = *(const uint32_t*)(stA + (r + 8) * ROWB + kb + 16);
            }
            uint32_t b[4][2];
            #pragma unroll
            for (int ni = 0; ni < 4; ni++) {
                int rn = n0 + ni * 8 + (l >> 2);
                b[ni][0] = *(const uint32_t*)(stB + rn * ROWB + kb);
                b[ni][1] = *(const uint32_t*)(stB + rn * ROWB + kb + 16);
            }
            #pragma unroll
            for (int mi = 0; mi < 2; mi++)
                #pragma unroll
                for (int ni = 0; ni < 4; ni++)
                    MMA_S8(c[mi][ni], a[mi], b[ni]);
        }
        __syncthreads();
    }

    // ---- fused epilogue: g warps -> silu to smem; u warps -> multiply+store --
    float* hf = (float*)smem;   // [128][EPI_STRIDE] = 33792 B < SMEM_DYN
    if (gsel == 0) {
        float sg = g_scales[0];
        #pragma unroll
        for (int mi = 0; mi < 2; mi++) {
            int r0 = m0 + mi * 16 + (l >> 2);
            int r1 = r0 + 8;
            float i0 = 1.f / (g_sa[tok0 + r0] * sg);
            float i1 = 1.f / (g_sa[tok0 + r1] * sg);
            #pragma unroll
            for (int ni = 0; ni < 4; ni++) {
                int col = n0 + ni * 8 + (l & 3) * 2;
                float g0 = (float)c[mi][ni][0] * i0;
                float g1 = (float)c[mi][ni][1] * i0;
                float g2 = (float)c[mi][ni][2] * i1;
                float g3 = (float)c[mi][ni][3] * i1;
                hf[r0 * EPI_STRIDE + col]     = g0 / (1.f + __expf(-g0));
                hf[r0 * EPI_STRIDE + col + 1] = g1 / (1.f + __expf(-g1));
                hf[r1 * EPI_STRIDE + col]     = g2 / (1.f + __expf(-g2));
                hf[r1 * EPI_STRIDE + col + 1] = g3 / (1.f + __expf(-g3));
            }
        }
    }
    __syncthreads();
    if (gsel == 1) {
        float su = g_scales[1];
        #pragma unroll
        for (int mi = 0; mi < 2; mi++) {
            int r0 = m0 + mi * 16 + (l >> 2);
            int r1 = r0 + 8;
            float i0 = 1.f / (g_sa[tok0 + r0] * su);
            float i1 = 1.f / (g_sa[tok0 + r1] * su);
            float* o0 = g_hbuf + (size_t)(tok0 + r0) * F_ + f0;
            float* o1 = g_hbuf + (size_t)(tok0 + r1) * F_ + f0;
            #pragma unroll
            for (int ni = 0; ni < 4; ni++) {
                int col = n0 + ni * 8 + (l & 3) * 2;
                float2 v0, v1;
                v0.x = hf[r0 * EPI_STRIDE + col]     * ((float)c[mi][ni][0] * i0);
                v0.y = hf[r0 * EPI_STRIDE + col + 1] * ((float)c[mi][ni][1] * i0);
                v1.x = hf[r1 * EPI_STRIDE + col]     * ((float)c[mi][ni][2] * i1);
                v1.y = hf[r1 * EPI_STRIDE + col + 1] * ((float)c[mi][ni][3] * i1);
                *(float2*)(o0 + col) = v0;
                *(float2*)(o1 + col) = v1;
            }
        }
    }
}

// ============ K7: rmsnorm + act-quant + dot(wd_sum)   grid 3072 x 256 ========
__global__ void __launch_bounds__(256) k_token(const float* __restrict__ lnw) {
    __shared__ float sh[F_];
    __shared__ float red[8];
    __shared__ float bc;
    int t = blockIdx.x, tid = threadIdx.x;
    int w = tid >> 5, l = tid & 31;
    const float4* src = (const float4*)(g_hbuf + (size_t)t * F_);
    float ss = 0.f;
    #pragma unroll
    for (int i = 0; i < 8; i++) {
        float4 v = src[i * 256 + tid];
        ((float4*)sh)[i * 256 + tid] = v;
        ss += v.x * v.x + v.y * v.y + v.z * v.z + v.w * v.w;
    }
    ss = warp_sum(ss);
    if (l == 0) red[w] = ss;
    __syncthreads();
    if (tid == 0) {
        float tot = 0.f;
        #pragma unroll
        for (int i = 0; i < 8; i++) tot += red[i];
        bc = rsqrtf(tot / (float)F_ + 1e-6f);
    }
    __syncthreads();
    float rs = bc;
    float am = 0.f;
    const float4* w4 = (const float4*)lnw;
    #pragma unroll
    for (int i = 0; i < 8; i++) {
        int idx = i * 256 + tid;
        float4 h = ((float4*)sh)[idx];
        float4 g = w4[idx];
        am = fmaxf(am, fabsf(h.x * rs * g.x));
        am = fmaxf(am, fabsf(h.y * rs * g.y));
        am = fmaxf(am, fabsf(h.z * rs * g.z));
        am = fmaxf(am, fabsf(h.w * rs * g.w));
    }
    am = warp_max(am);
    if (l == 0) red[w] = am;
    __syncthreads();
    if (tid == 0) {
        float m = red[0];
        #pragma unroll
        for (int i = 1; i < 8; i++) m = fmaxf(m, red[i]);
        bc = 127.f / fmaxf(m, 1e-5f);
    }
    __syncthreads();
    float s2 = bc;
    const float4* ws = (const float4*)g_wdsum;
    float acc = 0.f;
    #pragma unroll
    for (int i = 0; i < 8; i++) {
        int idx = i * 256 + tid;
        float4 h = ((float4*)sh)[idx];
        float4 g = w4[idx];
        float4 d = ws[idx];
        acc += fminf(fmaxf(rintf(h.x * rs * g.x * s2), -128.f), 127.f) * d.x;
        acc += fminf(fmaxf(rintf(h.y * rs * g.y * s2), -128.f), 127.f) * d.y;
        acc += fminf(fmaxf(rintf(h.z * rs * g.z * s2), -128.f), 127.f) * d.z;
        acc += fminf(fmaxf(rintf(h.w * rs * g.w * s2), -128.f), 127.f) * d.w;
    }
    acc = warp_sum(acc);
    if (l == 0) red[w] = acc;
    __syncthreads();
    if (tid == 0) {
        float tot = 0.f;
        #pragma unroll
        for (int i = 0; i < 8; i++) tot += red[i];
        g_tokval[t] = tot / s2;
    }
}

// ============ K8: pooled[b,c] ================================================
__global__ void k_pool() {
    int tid = threadIdx.x, w = tid >> 5, l = tid & 31;
    float inv = 1.f / (g_scales[2] * (float)H_ * (float)D_);
    for (int combo = w; combo < B_ * C_; combo += 8) {
        float s = 0.f;
        #pragma unroll
        for (int j = l; j < H_; j += 32) s += g_tokval[combo * H_ + j];
        s = warp_sum(s);
        if (l == 0) g_pooled[combo] = s * inv;
    }
}

// ============ K9: classifier =================================================
__global__ void k_cls(const float* __restrict__ cW, const float* __restrict__ cb,
                      float* __restrict__ out) {
    int i = blockIdx.x * 256 + threadIdx.x;
    if (i < B_ * NC_) {
        int b = i / NC_, n = i - b * NC_;
        float v = cb[n];
        v += g_pooled[b * 3 + 0] * cW[n * 3 + 0];
        v += g_pooled[b * 3 + 1] * cW[n * 3 + 1];
        v += g_pooled[b * 3 + 2] * cW[n * 3 + 2];
        out[i] = v;
    }
}

// ============ host ==========================================================
extern "C" void kernel_launch(void* const* d_in, const int* in_sizes, int n_in,
                              void* d_out, int out_size) {
    const float* x    = (const float*)d_in[0];
    const float* Wg   = (const float*)d_in[1];
    const float* Wu   = (const float*)d_in[2];
    const float* Wd   = (const float*)d_in[3];
    const float* lnw  = (const float*)d_in[4];
    const float* clsW = (const float*)d_in[5];
    const float* clsb = (const float*)d_in[6];
    float* out = (float*)d_out;

    cudaFuncSetAttribute(k_gemm, cudaFuncAttributeMaxDynamicSharedMemorySize, SMEM_DYN);

    k_zero<<<32, 256>>>();
    k_absmean<<<dim3(2048, 3), 256>>>(Wg, Wu, Wd);
    k_scales<<<1, 256>>>();
    k_quantw<<<dim3(2048, 2), 256>>>(Wg, Wu);
    k_wdsum<<<512, 256>>>(Wd);
    k_xquant<<<TOK, 256>>>(x);
    k_gemm<<<dim3(F_ / TILE_N, TOK / TILE_M), 512, SMEM_DYN>>>();
    k_token<<<TOK, 256>>>(lnw);
    k_pool<<<1, 256>>>();
    k_cls<<<32, 256>>>(clsW, clsb, out);
}